// round 5
// baseline (speedup 1.0000x reference)
#include <cuda_runtime.h>
#include <cstdint>
#include <math.h>

// Problem constants (fixed by the dataset)
#define BATCH 4
#define SEQL  2048
#define NH    8
#define HDIM  64      // E == D == 64
#define BM    128     // query rows per CTA (8 warps x 16 rows)
#define BN    64      // key rows per iteration
#define NT    256
#define RST   68      // raw K/V row stride (floats)
#define KP    68      // permuted K row stride
#define VP    68      // permuted V row stride
#define RS    (NH * HDIM)   // 512 floats between seq positions

// smem layout (floats)
#define RAW0    0
#define RAW1    (2 * BN * RST)          //  8704
#define PERMK   (4 * BN * RST)          // 17408
#define PERMV   (PERMK + BN * KP)       // 21760
#define SMEM_FLOATS (PERMV + BN * VP)   // 26112
#define SMEM_BYTES  (SMEM_FLOATS * 4)   // 104448

__device__ __forceinline__ uint32_t f2tf32(float f) {
    uint32_t u;
    asm("cvt.rna.tf32.f32 %0, %1;" : "=r"(u) : "f"(f));
    return u;
}
__device__ __forceinline__ float f2tf32f(float f) {
    return __uint_as_float(f2tf32(f));
}
__device__ __forceinline__ float ex2(float x) {
    float y;
    asm("ex2.approx.ftz.f32 %0, %1;" : "=f"(y) : "f"(x));
    return y;
}

__device__ __forceinline__ void mma8(float c[4], const uint32_t a[4], const uint32_t b[2]) {
    asm volatile(
        "mma.sync.aligned.m16n8k8.row.col.f32.tf32.tf32.f32 "
        "{%0,%1,%2,%3}, {%4,%5,%6,%7}, {%8,%9}, {%0,%1,%2,%3};"
        : "+f"(c[0]), "+f"(c[1]), "+f"(c[2]), "+f"(c[3])
        : "r"(a[0]), "r"(a[1]), "r"(a[2]), "r"(a[3]),
          "r"(b[0]), "r"(b[1]));
}

__device__ __forceinline__ void cpasync16(uint32_t saddr, const float* g) {
    asm volatile("cp.async.cg.shared.global [%0], [%1], 16;\n"
                 :: "r"(saddr), "l"(g));
}

__global__ __launch_bounds__(NT, 1)
void fa_tf32_kernel(const float* __restrict__ Q,
                    const float* __restrict__ K,
                    const float* __restrict__ V,
                    float* __restrict__ O)
{
    extern __shared__ float smem[];

    const int tid  = threadIdx.x;
    const int warp = tid >> 5;
    const int lane = tid & 31;
    const int qd   = lane & 3;    // thread-in-group
    const int g    = lane >> 2;   // group id

    const int bh = blockIdx.y;
    const int b  = bh >> 3;       // NH = 8
    const int h  = bh & 7;
    // heavy tiles first
    const int qblk = (SEQL / BM - 1) - blockIdx.x;
    const int m0   = qblk * BM;
    const int nblk = 2 * qblk + 2;     // key tiles 0 .. 2*qblk+1

    const float sc = 0.125f * 1.4426950408889634f;   // (1/sqrt(64)) * log2(e)

    const float* Qb = Q + ((size_t)((size_t)b * SEQL + m0) * NH + h) * HDIM;
    const float* Kb = K + ((size_t)((size_t)b * SEQL) * NH + h) * HDIM;
    const float* Vb = V + ((size_t)((size_t)b * SEQL) * NH + h) * HDIM;

    float* const raw0 = smem + RAW0;
    float* const raw1 = smem + RAW1;
    float* const pK   = smem + PERMK;
    float* const pV   = smem + PERMV;

    // ---- prologue: async-load K/V tile 0 into raw0 (raw, padded stride)
    #pragma unroll
    for (int k = 0; k < 4; k++) {
        int q  = tid + k * NT;         // 0..1023 chunk id
        int r  = q >> 4;
        int c4 = (q & 15) << 2;
        size_t goff = (size_t)r * RS + c4;
        cpasync16((uint32_t)__cvta_generic_to_shared(raw0 + r * RST + c4), Kb + goff);
        cpasync16((uint32_t)__cvta_generic_to_shared(raw0 + BN * RST + r * RST + c4), Vb + goff);
    }
    asm volatile("cp.async.commit_group;\n");

    // ---- stage Q (raw) into permuted area (128 rows x stride 68), lift tf32 frags
    #pragma unroll
    for (int k = 0; k < 8; k++) {
        int q  = tid + k * NT;         // 0..2047 chunk id (128 rows x 16)
        int r  = q >> 4;
        int c4 = (q & 15) << 2;
        float4 v = *reinterpret_cast<const float4*>(Qb + (size_t)r * RS + c4);
        float* dst = &pK[r * 68 + c4];   // pK..pV contiguous: 128*68 floats
        dst[0] = v.x; dst[1] = v.y; dst[2] = v.z; dst[3] = v.w;
    }
    __syncthreads();

    const int r0    = warp * 16 + g;      // tile-local row (and r0+8)
    const int grow0 = m0 + r0;
    const int grow1 = grow0 + 8;

    uint32_t qa[8][4];
    #pragma unroll
    for (int kk = 0; kk < 8; kk++) {
        qa[kk][0] = f2tf32(pK[r0       * 68 + kk * 8 + qd]);
        qa[kk][1] = f2tf32(pK[(r0 + 8) * 68 + kk * 8 + qd]);
        qa[kk][2] = f2tf32(pK[r0       * 68 + kk * 8 + qd + 4]);
        qa[kk][3] = f2tf32(pK[(r0 + 8) * 68 + kk * 8 + qd + 4]);
    }
    __syncthreads();   // Q fully consumed before permute pass overwrites pK/pV

    float o[8][4];
    #pragma unroll
    for (int n = 0; n < 8; n++)
        #pragma unroll
        for (int i = 0; i < 4; i++) o[n][i] = 0.f;

    float mrow0 = -INFINITY, mrow1 = -INFINITY;
    float l0 = 0.f, l1 = 0.f;

    for (int j = 0; j < nblk; j++) {
        float* const raw = (j & 1) ? raw1 : raw0;
        float* const rK  = raw;
        float* const rV  = raw + BN * RST;

        asm volatile("cp.async.wait_group 0;\n");
        __syncthreads();   // tile j raw visible; all warps done with prior P (in other raw)

        // ---- prefetch tile j+1 into the other raw stage
        if (j + 1 < nblk) {
            float* const nraw = (j & 1) ? raw0 : raw1;
            #pragma unroll
            for (int k = 0; k < 4; k++) {
                int q  = tid + k * NT;
                int r  = q >> 4;
                int c4 = (q & 15) << 2;
                size_t goff = (size_t)((j + 1) * BN + r) * RS + c4;
                cpasync16((uint32_t)__cvta_generic_to_shared(nraw + r * RST + c4), Kb + goff);
                cpasync16((uint32_t)__cvta_generic_to_shared(nraw + BN * RST + r * RST + c4), Vb + goff);
            }
            asm volatile("cp.async.commit_group;\n");
        }

        // ---- permute + convert pass: raw -> pK (chunk-of-16 by c mod 4),
        //      raw -> pV (chunk-of-8 by c mod 8). Each element once per CTA.
        #pragma unroll
        for (int k = 0; k < 4; k++) {
            int q  = tid + k * NT;
            int r  = q >> 4;
            int c4 = (q & 15) << 2;
            int w  = c4 >> 2;
            float4 kv = *reinterpret_cast<const float4*>(rK + r * RST + c4);
            pK[r * KP + w]      = f2tf32f(kv.x);
            pK[r * KP + 16 + w] = f2tf32f(kv.y);
            pK[r * KP + 32 + w] = f2tf32f(kv.z);
            pK[r * KP + 48 + w] = f2tf32f(kv.w);
            int b8 = c4 & 7;          // 0 or 4
            int w8 = c4 >> 3;
            float4 vv = *reinterpret_cast<const float4*>(rV + r * RST + c4);
            pV[r * VP + 8 * (b8 + 0) + w8] = f2tf32f(vv.x);
            pV[r * VP + 8 * (b8 + 1) + w8] = f2tf32f(vv.y);
            pV[r * VP + 8 * (b8 + 2) + w8] = f2tf32f(vv.z);
            pV[r * VP + 8 * (b8 + 3) + w8] = f2tf32f(vv.w);
        }
        __syncthreads();   // permuted tile visible; raw tile now dead (P parks there)

        // ---- S = Q K^T : vectorized B-frag reads (4x LDS.128 per n)
        float c[8][4];
        #pragma unroll
        for (int n = 0; n < 8; n++)
            #pragma unroll
            for (int i = 0; i < 4; i++) c[n][i] = 0.f;

        #pragma unroll
        for (int n = 0; n < 8; n++) {
            const float* rowp = &pK[(n * 8 + g) * KP + 16 * qd];
            float f[16];
            *reinterpret_cast<float4*>(&f[0])  = *reinterpret_cast<const float4*>(rowp);
            *reinterpret_cast<float4*>(&f[4])  = *reinterpret_cast<const float4*>(rowp + 4);
            *reinterpret_cast<float4*>(&f[8])  = *reinterpret_cast<const float4*>(rowp + 8);
            *reinterpret_cast<float4*>(&f[12]) = *reinterpret_cast<const float4*>(rowp + 12);
            #pragma unroll
            for (int kk = 0; kk < 8; kk++) {
                uint32_t bf[2];
                bf[0] = __float_as_uint(f[2 * kk]);
                bf[1] = __float_as_uint(f[2 * kk + 1]);
                mma8(c[n], qa[kk], bf);
            }
        }

        // ---- causal mask (last two key tiles only)
        if (j >= 2 * qblk) {
            #pragma unroll
            for (int n = 0; n < 8; n++) {
                int colb = j * BN + n * 8 + 2 * qd;
                if (colb     > grow0) c[n][0] = -INFINITY;
                if (colb + 1 > grow0) c[n][1] = -INFINITY;
                if (colb     > grow1) c[n][2] = -INFINITY;
                if (colb + 1 > grow1) c[n][3] = -INFINITY;
            }
        }

        // ---- online softmax
        float tm0 = -INFINITY, tm1 = -INFINITY;
        #pragma unroll
        for (int n = 0; n < 8; n++) {
            tm0 = fmaxf(tm0, fmaxf(c[n][0], c[n][1]));
            tm1 = fmaxf(tm1, fmaxf(c[n][2], c[n][3]));
        }
        tm0 = fmaxf(tm0, __shfl_xor_sync(0xffffffffu, tm0, 1));
        tm0 = fmaxf(tm0, __shfl_xor_sync(0xffffffffu, tm0, 2));
        tm1 = fmaxf(tm1, __shfl_xor_sync(0xffffffffu, tm1, 1));
        tm1 = fmaxf(tm1, __shfl_xor_sync(0xffffffffu, tm1, 2));

        float mn0 = fmaxf(mrow0, tm0);
        float mn1 = fmaxf(mrow1, tm1);
        float a0 = ex2((mrow0 - mn0) * sc);
        float a1 = ex2((mrow1 - mn1) * sc);
        mrow0 = mn0; mrow1 = mn1;
        l0 *= a0;  l1 *= a1;

        #pragma unroll
        for (int n = 0; n < 8; n++) {
            o[n][0] *= a0; o[n][1] *= a0;
            o[n][2] *= a1; o[n][3] *= a1;
            float p0 = ex2((c[n][0] - mn0) * sc);
            float p1 = ex2((c[n][1] - mn0) * sc);
            float p2 = ex2((c[n][2] - mn1) * sc);
            float p3 = ex2((c[n][3] - mn1) * sc);
            l0 += p0 + p1;
            l1 += p2 + p3;
            c[n][0] = p0; c[n][1] = p1; c[n][2] = p2; c[n][3] = p3;
        }

        // ---- park P (tf32) in the DEAD raw stage (128 rows x stride 68).
        // Each warp only touches its own rows -> __syncwarp suffices.
        float* const sP = raw;
        #pragma unroll
        for (int n = 0; n < 8; n++) {
            *reinterpret_cast<float2*>(&sP[r0       * RST + n * 8 + 2 * qd]) =
                make_float2(f2tf32f(c[n][0]), f2tf32f(c[n][1]));
            *reinterpret_cast<float2*>(&sP[(r0 + 8) * RST + n * 8 + 2 * qd]) =
                make_float2(f2tf32f(c[n][2]), f2tf32f(c[n][3]));
        }
        __syncwarp();

        // ---- O += P V : vectorized V B-frag reads (4x LDS.128 per kk)
        #pragma unroll
        for (int kk = 0; kk < 8; kk++) {
            uint32_t pa[4];
            pa[0] = __float_as_uint(sP[r0       * RST + kk * 8 + qd]);
            pa[1] = __float_as_uint(sP[(r0 + 8) * RST + kk * 8 + qd]);
            pa[2] = __float_as_uint(sP[r0       * RST + kk * 8 + qd + 4]);
            pa[3] = __float_as_uint(sP[(r0 + 8) * RST + kk * 8 + qd + 4]);
            const float* v0p = &pV[(kk * 8 + qd)     * VP + 8 * g];
            const float* v1p = &pV[(kk * 8 + qd + 4) * VP + 8 * g];
            float f0[8], f1[8];
            *reinterpret_cast<float4*>(&f0[0]) = *reinterpret_cast<const float4*>(v0p);
            *reinterpret_cast<float4*>(&f0[4]) = *reinterpret_cast<const float4*>(v0p + 4);
            *reinterpret_cast<float4*>(&f1[0]) = *reinterpret_cast<const float4*>(v1p);
            *reinterpret_cast<float4*>(&f1[4]) = *reinterpret_cast<const float4*>(v1p + 4);
            #pragma unroll
            for (int n = 0; n < 8; n++) {
                uint32_t vb[2];
                vb[0] = __float_as_uint(f0[n]);
                vb[1] = __float_as_uint(f1[n]);
                mma8(o[n], pa, vb);
            }
        }
    }

    // ---- finalize: reduce l across the quad, normalize, store
    l0 += __shfl_xor_sync(0xffffffffu, l0, 1);
    l0 += __shfl_xor_sync(0xffffffffu, l0, 2);
    l1 += __shfl_xor_sync(0xffffffffu, l1, 1);
    l1 += __shfl_xor_sync(0xffffffffu, l1, 2);
    const float inv0 = 1.f / l0;
    const float inv1 = 1.f / l1;

    float* Ob0 = O + ((size_t)((size_t)b * SEQL + grow0) * NH + h) * HDIM;
    float* Ob1 = O + ((size_t)((size_t)b * SEQL + grow1) * NH + h) * HDIM;
    #pragma unroll
    for (int n = 0; n < 8; n++) {
        int col = n * 8 + 2 * qd;
        *reinterpret_cast<float2*>(Ob0 + col) =
            make_float2(o[n][0] * inv0, o[n][1] * inv0);
        *reinterpret_cast<float2*>(Ob1 + col) =
            make_float2(o[n][2] * inv1, o[n][3] * inv1);
    }
}

extern "C" void kernel_launch(void* const* d_in, const int* in_sizes, int n_in,
                              void* d_out, int out_size)
{
    const float* Q = (const float*)d_in[0];
    const float* K = (const float*)d_in[1];
    const float* V = (const float*)d_in[2];
    float* O = (float*)d_out;

    cudaFuncSetAttribute(fa_tf32_kernel,
                         cudaFuncAttributeMaxDynamicSharedMemorySize, SMEM_BYTES);

    dim3 grid(SEQL / BM, BATCH * NH);   // (16, 32)
    dim3 block(NT);
    fa_tf32_kernel<<<grid, block, SMEM_BYTES>>>(Q, K, V, O);
}

// round 6
// speedup vs baseline: 1.8959x; 1.8959x over previous
#include <cuda_runtime.h>
#include <cstdint>
#include <math.h>

// Problem constants (fixed by the dataset)
#define BATCH 4
#define SEQL  2048
#define NH    8
#define HDIM  64      // E == D == 64
#define BM    64      // query rows per CTA
#define BN    64      // key rows per iteration
#define KSTR  68      // sK row stride (floats) — conflict-free for QK B-frags & P A-frags
#define VSTR  72      // sV row stride (floats) — conflict-free for PV B-frags
#define RS    (NH * HDIM)           // 512 floats between seq positions
#define STAGE_FLOATS (BN * KSTR + BN * VSTR)   // 8960 floats per stage
#define SMEM_BYTES (2 * STAGE_FLOATS * 4)      // 71680 bytes

__device__ __forceinline__ uint32_t f2tf32(float f) {
    uint32_t u;
    asm("cvt.rna.tf32.f32 %0, %1;" : "=r"(u) : "f"(f));
    return u;
}
__device__ __forceinline__ float ex2(float x) {
    float y;
    asm("ex2.approx.ftz.f32 %0, %1;" : "=f"(y) : "f"(x));
    return y;
}

__device__ __forceinline__ void mma8(float c[4], const uint32_t a[4], const uint32_t b[2]) {
    asm volatile(
        "mma.sync.aligned.m16n8k8.row.col.f32.tf32.tf32.f32 "
        "{%0,%1,%2,%3}, {%4,%5,%6,%7}, {%8,%9}, {%0,%1,%2,%3};"
        : "+f"(c[0]), "+f"(c[1]), "+f"(c[2]), "+f"(c[3])
        : "r"(a[0]), "r"(a[1]), "r"(a[2]), "r"(a[3]),
          "r"(b[0]), "r"(b[1]));
}

__device__ __forceinline__ void cpasync16(uint32_t saddr, const float* g) {
    asm volatile("cp.async.cg.shared.global [%0], [%1], 16;\n"
                 :: "r"(saddr), "l"(g));
}

__global__ __launch_bounds__(128, 3)
void fa_tf32_kernel(const float* __restrict__ Q,
                    const float* __restrict__ K,
                    const float* __restrict__ V,
                    float* __restrict__ O)
{
    extern __shared__ float smem[];

    const int tid  = threadIdx.x;
    const int warp = tid >> 5;
    const int lane = tid & 31;
    const int qd   = lane & 3;    // thread-in-group
    const int g    = lane >> 2;   // group id

    const int bh = blockIdx.y;
    const int b  = bh >> 3;       // NH = 8
    const int h  = bh & 7;
    // heavy tiles first: block 0 handles the longest causal row
    const int qblk = (SEQL / BM - 1) - blockIdx.x;
    const int m0   = qblk * BM;
    const int nblk = qblk + 1;

    // fold softmax scale into Q: scores come out already in log2 domain
    const float qscale = 0.125f * 1.4426950408889634f;   // (1/sqrt(64)) * log2(e)

    const float* Qb = Q + ((size_t)((size_t)b * SEQL + m0) * NH + h) * HDIM;
    const float* Kb = K + ((size_t)((size_t)b * SEQL) * NH + h) * HDIM;
    const float* Vb = V + ((size_t)((size_t)b * SEQL) * NH + h) * HDIM;

    float* const stage0 = smem;
    float* const stage1 = smem + STAGE_FLOATS;

    // ---- prologue: async-load K/V block 0 into stage0
    {
        #pragma unroll
        for (int i = 0; i < 8; i++) {
            int idx = i * 128 + tid;
            int r   = idx >> 4;
            int c4  = (idx & 15) << 2;
            size_t goff = (size_t)r * RS + c4;
            cpasync16((uint32_t)__cvta_generic_to_shared(stage0 + r * KSTR + c4), Kb + goff);
            cpasync16((uint32_t)__cvta_generic_to_shared(stage0 + BN * KSTR + r * VSTR + c4), Vb + goff);
        }
        asm volatile("cp.async.commit_group;\n");
    }

    // ---- stage Q (raw) into stage1's sK area, lift to scaled tf32 A-frags
    #pragma unroll
    for (int i = 0; i < 8; i++) {
        int idx = i * 128 + tid;
        int r   = idx >> 4;
        int c4  = (idx & 15) << 2;
        float4 v = *reinterpret_cast<const float4*>(Qb + (size_t)r * RS + c4);
        float* dst = &stage1[r * KSTR + c4];
        dst[0] = v.x; dst[1] = v.y; dst[2] = v.z; dst[3] = v.w;
    }
    __syncthreads();

    const int r0    = warp * 16 + g;      // tile-local row (and r0+8)
    const int grow0 = m0 + r0;
    const int grow1 = grow0 + 8;

    uint32_t qa[8][4];
    #pragma unroll
    for (int kk = 0; kk < 8; kk++) {
        qa[kk][0] = f2tf32(stage1[r0       * KSTR + kk * 8 + qd]     * qscale);
        qa[kk][1] = f2tf32(stage1[(r0 + 8) * KSTR + kk * 8 + qd]     * qscale);
        qa[kk][2] = f2tf32(stage1[r0       * KSTR + kk * 8 + qd + 4] * qscale);
        qa[kk][3] = f2tf32(stage1[(r0 + 8) * KSTR + kk * 8 + qd + 4] * qscale);
    }
    __syncthreads();   // all warps done with Q in stage1 before j=1 load lands there

    float o[8][4];
    #pragma unroll
    for (int n = 0; n < 8; n++)
        #pragma unroll
        for (int i = 0; i < 4; i++) o[n][i] = 0.f;

    float mrow0 = -INFINITY, mrow1 = -INFINITY;
    float l0 = 0.f, l1 = 0.f;

    for (int j = 0; j < nblk; j++) {
        float* const sK = (j & 1) ? stage1 : stage0;
        float* const sV = sK + BN * KSTR;

        asm volatile("cp.async.wait_group 0;\n");
        __syncthreads();   // stage j data visible to all; prior reads of other stage done

        // ---- prefetch block j+1 into the other stage (overlaps with compute)
        if (j + 1 < nblk) {
            float* const nK = (j & 1) ? stage0 : stage1;
            float* const nV = nK + BN * KSTR;
            #pragma unroll
            for (int i = 0; i < 8; i++) {
                int idx = i * 128 + tid;
                int r   = idx >> 4;
                int c4  = (idx & 15) << 2;
                size_t goff = (size_t)((j + 1) * BN + r) * RS + c4;
                cpasync16((uint32_t)__cvta_generic_to_shared(nK + r * KSTR + c4), Kb + goff);
                cpasync16((uint32_t)__cvta_generic_to_shared(nV + r * VSTR + c4), Vb + goff);
            }
            asm volatile("cp.async.commit_group;\n");
        }

        // ---- S = Q K^T  (16x64 per warp); K fed RAW to the tf32 MMA
        // (hardware reads bits[31:13] -> RZ truncation to tf32; no CVT needed)
        float c[8][4];
        #pragma unroll
        for (int n = 0; n < 8; n++)
            #pragma unroll
            for (int i = 0; i < 4; i++) c[n][i] = 0.f;

        #pragma unroll
        for (int kk = 0; kk < 8; kk++) {
            #pragma unroll
            for (int n = 0; n < 8; n++) {
                uint32_t bf[2];
                bf[0] = __float_as_uint(sK[(n * 8 + g) * KSTR + kk * 8 + qd]);
                bf[1] = __float_as_uint(sK[(n * 8 + g) * KSTR + kk * 8 + qd + 4]);
                mma8(c[n], qa[kk], bf);
            }
        }

        // ---- causal mask (diagonal block only)
        if (j == qblk) {
            #pragma unroll
            for (int n = 0; n < 8; n++) {
                int colb = j * BN + n * 8 + 2 * qd;
                if (colb     > grow0) c[n][0] = -INFINITY;
                if (colb + 1 > grow0) c[n][1] = -INFINITY;
                if (colb     > grow1) c[n][2] = -INFINITY;
                if (colb + 1 > grow1) c[n][3] = -INFINITY;
            }
        }

        // ---- online softmax (scores already scaled & in log2 domain)
        float tm0 = -INFINITY, tm1 = -INFINITY;
        #pragma unroll
        for (int n = 0; n < 8; n++) {
            tm0 = fmaxf(tm0, fmaxf(c[n][0], c[n][1]));
            tm1 = fmaxf(tm1, fmaxf(c[n][2], c[n][3]));
        }
        tm0 = fmaxf(tm0, __shfl_xor_sync(0xffffffffu, tm0, 1));
        tm0 = fmaxf(tm0, __shfl_xor_sync(0xffffffffu, tm0, 2));
        tm1 = fmaxf(tm1, __shfl_xor_sync(0xffffffffu, tm1, 1));
        tm1 = fmaxf(tm1, __shfl_xor_sync(0xffffffffu, tm1, 2));

        float mn0 = fmaxf(mrow0, tm0);
        float mn1 = fmaxf(mrow1, tm1);
        float a0 = ex2(mrow0 - mn0);
        float a1 = ex2(mrow1 - mn1);
        mrow0 = mn0; mrow1 = mn1;
        l0 *= a0;  l1 *= a1;

        #pragma unroll
        for (int n = 0; n < 8; n++) {
            o[n][0] *= a0; o[n][1] *= a0;
            o[n][2] *= a1; o[n][3] *= a1;
            float p0 = ex2(c[n][0] - mn0);
            float p1 = ex2(c[n][1] - mn0);
            float p2 = ex2(c[n][2] - mn1);
            float p3 = ex2(c[n][3] - mn1);
            l0 += p0 + p1;
            l1 += p2 + p3;
            c[n][0] = p0; c[n][1] = p1; c[n][2] = p2; c[n][3] = p3;
        }

        // ---- write P (raw fp32 bits; MMA truncates) over the dead K tile
        __syncthreads();   // all warps done reading K fragments from sK
        #pragma unroll
        for (int n = 0; n < 8; n++) {
            *reinterpret_cast<float2*>(&sK[r0       * KSTR + n * 8 + 2 * qd]) =
                make_float2(c[n][0], c[n][1]);
            *reinterpret_cast<float2*>(&sK[(r0 + 8) * KSTR + n * 8 + 2 * qd]) =
                make_float2(c[n][2], c[n][3]);
        }
        __syncwarp();      // each warp only reads its own 16 P rows

        // ---- O += P V  (P and V fed raw; truncation inside the MMA)
        #pragma unroll
        for (int kk = 0; kk < 8; kk++) {
            uint32_t pa[4];
            pa[0] = __float_as_uint(sK[r0       * KSTR + kk * 8 + qd]);
            pa[1] = __float_as_uint(sK[(r0 + 8) * KSTR + kk * 8 + qd]);
            pa[2] = __float_as_uint(sK[r0       * KSTR + kk * 8 + qd + 4]);
            pa[3] = __float_as_uint(sK[(r0 + 8) * KSTR + kk * 8 + qd + 4]);
            #pragma unroll
            for (int n = 0; n < 8; n++) {
                uint32_t vb[2];
                vb[0] = __float_as_uint(sV[(kk * 8 + qd)     * VSTR + n * 8 + g]);
                vb[1] = __float_as_uint(sV[(kk * 8 + qd + 4) * VSTR + n * 8 + g]);
                mma8(o[n], pa, vb);
            }
        }
    }

    // ---- finalize: reduce l across the quad, normalize, store
    l0 += __shfl_xor_sync(0xffffffffu, l0, 1);
    l0 += __shfl_xor_sync(0xffffffffu, l0, 2);
    l1 += __shfl_xor_sync(0xffffffffu, l1, 1);
    l1 += __shfl_xor_sync(0xffffffffu, l1, 2);
    const float inv0 = 1.f / l0;
    const float inv1 = 1.f / l1;

    float* Ob0 = O + ((size_t)((size_t)b * SEQL + grow0) * NH + h) * HDIM;
    float* Ob1 = O + ((size_t)((size_t)b * SEQL + grow1) * NH + h) * HDIM;
    #pragma unroll
    for (int n = 0; n < 8; n++) {
        int col = n * 8 + 2 * qd;
        *reinterpret_cast<float2*>(Ob0 + col) =
            make_float2(o[n][0] * inv0, o[n][1] * inv0);
        *reinterpret_cast<float2*>(Ob1 + col) =
            make_float2(o[n][2] * inv1, o[n][3] * inv1);
    }
}

extern "C" void kernel_launch(void* const* d_in, const int* in_sizes, int n_in,
                              void* d_out, int out_size)
{
    const float* Q = (const float*)d_in[0];
    const float* K = (const float*)d_in[1];
    const float* V = (const float*)d_in[2];
    float* O = (float*)d_out;

    cudaFuncSetAttribute(fa_tf32_kernel,
                         cudaFuncAttributeMaxDynamicSharedMemorySize, SMEM_BYTES);

    dim3 grid(SEQL / BM, BATCH * NH);   // (32, 32)
    dim3 block(128);
    fa_tf32_kernel<<<grid, block, SMEM_BYTES>>>(Q, K, V, O);
}